// round 1
// baseline (speedup 1.0000x reference)
#include <cuda_runtime.h>

// ---------------------------------------------------------------------------
// DeformableBlock: offset conv3x3 (256->18) + deformable conv v1 (256->256,3x3)
//                  + GroupNorm(32) + ReLU.   B=4, C=256, H=W=64.
// Strategy R0: fp32 pipeline.
//   x NCHW -> NHWC; offsets via tiled direct conv; bilinear im2col into scratch
//   A[16384 x 2304]; SIMT fp32 GEMM A @ Wt[2304 x 256]; GN stats + epilogue.
// ---------------------------------------------------------------------------

#define BATCH 4
#define CIN   256
#define COUT  256
#define HH    64
#define WW    64
#define HWSZ  (HH*WW)          // 4096
#define NPIX  (BATCH*HWSZ)     // 16384
#define KT    9
#define KDIM  (KT*CIN)         // 2304
#define OCOFF 18
#define GROUPS 32
#define CPG   (COUT/GROUPS)    // 8

// scratch (static device allocations only; no cudaMalloc allowed)
__device__ float g_xt  [NPIX * CIN];          // x in NHWC           16.8 MB
__device__ float g_off [NPIX * OCOFF];        // offsets per pixel    1.2 MB
__device__ float g_wt  [KDIM * COUT];         // W^T  [k*256+c][o]    2.4 MB
__device__ float g_A   [NPIX * KDIM];         // bilinear im2col    151.0 MB
__device__ float g_P   [NPIX * COUT];         // pre-GN result       16.8 MB
__device__ float g_stat[BATCH * GROUPS * 2];  // mean / rstd

// ---------------------------------------------------------------------------
// K0: x NCHW -> NHWC  (per-batch 256 x 4096 transpose, 32x32 tiles)
// ---------------------------------------------------------------------------
__global__ void k_transpose_x(const float* __restrict__ x) {
    __shared__ float tile[32][33];
    int b   = blockIdx.z;
    int hw0 = blockIdx.x * 32;
    int c0  = blockIdx.y * 32;
    int tx  = threadIdx.x, ty = threadIdx.y;
#pragma unroll
    for (int i = 0; i < 4; i++) {
        int c = c0 + ty + i * 8;
        tile[ty + i * 8][tx] = x[((long)b * CIN + c) * HWSZ + hw0 + tx];
    }
    __syncthreads();
#pragma unroll
    for (int i = 0; i < 4; i++) {
        int hw = hw0 + ty + i * 8;
        g_xt[((long)b * HWSZ + hw) * CIN + c0 + tx] = tile[tx][ty + i * 8];
    }
}

// ---------------------------------------------------------------------------
// K0b: deform_w [O][C][3][3] -> g_wt[(k*256+c)*256 + o]
// ---------------------------------------------------------------------------
__global__ void k_transpose_w(const float* __restrict__ dw) {
    int idx = blockIdx.x * blockDim.x + threadIdx.x;
    if (idx >= KDIM * COUT) return;
    int o = idx & 255;
    int c = (idx >> 8) & 255;
    int k = idx >> 16;
    g_wt[idx] = dw[(o * CIN + c) * KT + k];
}

// ---------------------------------------------------------------------------
// K1: offset conv 3x3 (CIN=256 -> 18) + bias, pad=1.  NHWC input.
// 16x16 spatial tile per block, c-chunks of 8.  Weights broadcast via float4.
// ---------------------------------------------------------------------------
__global__ __launch_bounds__(256) void k_offset_conv(
    const float* __restrict__ ow, const float* __restrict__ ob) {
    int b  = blockIdx.z;
    int x0 = blockIdx.x * 16;
    int y0 = blockIdx.y * 16;
    int tid = threadIdx.x;
    int tx = tid & 15, ty = tid >> 4;

    __shared__ float sx[8][18][18];
    __shared__ float swf[8 * 9 * 20];   // [cc][j][oc(20, 18 used)]

    float acc[20];
#pragma unroll
    for (int i = 0; i < 20; i++) acc[i] = 0.f;

    for (int c0 = 0; c0 < CIN; c0 += 8) {
        // cooperative load of x tile with halo (zero-padded)
        for (int i = tid; i < 18 * 18 * 8; i += 256) {
            int cc = i & 7, p = i >> 3;
            int xx = p % 18, yy = p / 18;
            int gy = y0 + yy - 1, gx = x0 + xx - 1;
            float v = 0.f;
            if (gy >= 0 && gy < HH && gx >= 0 && gx < WW)
                v = g_xt[((b * HWSZ) + gy * WW + gx) * CIN + c0 + cc];
            sx[cc][yy][xx] = v;
        }
        // weights for this chunk
        for (int i = tid; i < 8 * 9 * 20; i += 256) {
            int oc = i % 20, j = (i / 20) % 9, cc = i / 180;
            swf[i] = (oc < OCOFF) ? ow[(oc * CIN + c0 + cc) * KT + j] : 0.f;
        }
        __syncthreads();
#pragma unroll
        for (int cc = 0; cc < 8; cc++) {
            float v[9];
#pragma unroll
            for (int j = 0; j < 9; j++)
                v[j] = sx[cc][ty + j / 3][tx + j % 3];
#pragma unroll
            for (int j = 0; j < 9; j++) {
                const float4* wp = reinterpret_cast<const float4*>(&swf[(cc * 9 + j) * 20]);
#pragma unroll
                for (int q = 0; q < 5; q++) {
                    float4 w = wp[q];
                    acc[q * 4 + 0] += v[j] * w.x;
                    acc[q * 4 + 1] += v[j] * w.y;
                    acc[q * 4 + 2] += v[j] * w.z;
                    acc[q * 4 + 3] += v[j] * w.w;
                }
            }
        }
        __syncthreads();
    }
    int pix = b * HWSZ + (y0 + ty) * WW + (x0 + tx);
#pragma unroll
    for (int oc = 0; oc < OCOFF; oc++)
        g_off[pix * OCOFF + oc] = acc[oc] + ob[oc];
}

// ---------------------------------------------------------------------------
// K2: bilinear im2col.  One block per (b, h, tap).  Threads = channels.
//     A[pix][k*256+c] = bilinear sample of x at (h-1+ky+dy, w-1+kx+dx).
// ---------------------------------------------------------------------------
__global__ __launch_bounds__(256) void k_sample() {
    int bk = blockIdx.x;
    int k  = bk % 9;
    int h  = (bk / 9) & 63;
    int b  = bk / (9 * 64);

    __shared__ int   sI[4][64];
    __shared__ float sWt[4][64];
    int tid = threadIdx.x;

    if (tid < 64) {
        int w = tid;
        int pix = b * HWSZ + h * WW + w;
        float dy = g_off[pix * OCOFF + 2 * k];
        float dx = g_off[pix * OCOFF + 2 * k + 1];
        int ky = k / 3, kx = k % 3;
        float py = (float)(h - 1 + ky) + dy;
        float px = (float)(w - 1 + kx) + dx;
        float y0f = floorf(py), x0f = floorf(px);
        float ty = py - y0f, tx = px - x0f;
        int y0 = (int)y0f, x0 = (int)x0f;
        int y1 = y0 + 1, x1 = x0 + 1;
        float vy0 = (y0 >= 0 && y0 < HH) ? 1.f : 0.f;
        float vy1 = (y1 >= 0 && y1 < HH) ? 1.f : 0.f;
        float vx0 = (x0 >= 0 && x0 < WW) ? 1.f : 0.f;
        float vx1 = (x1 >= 0 && x1 < WW) ? 1.f : 0.f;
        int yc0 = min(max(y0, 0), HH - 1), yc1 = min(max(y1, 0), HH - 1);
        int xc0 = min(max(x0, 0), WW - 1), xc1 = min(max(x1, 0), WW - 1);
        sI[0][w] = yc0 * WW + xc0;  sWt[0][w] = (1.f - ty) * (1.f - tx) * vy0 * vx0;
        sI[1][w] = yc0 * WW + xc1;  sWt[1][w] = (1.f - ty) * tx * vy0 * vx1;
        sI[2][w] = yc1 * WW + xc0;  sWt[2][w] = ty * (1.f - tx) * vy1 * vx0;
        sI[3][w] = yc1 * WW + xc1;  sWt[3][w] = ty * tx * vy1 * vx1;
    }
    __syncthreads();

    int c = tid;
    const float* xb = &g_xt[(long)b * HWSZ * CIN];
    long rowbase = ((long)(b * HWSZ + h * WW)) * KDIM + k * CIN + c;
#pragma unroll 2
    for (int w = 0; w < 64; w++) {
        float s = sWt[0][w] * xb[sI[0][w] * CIN + c]
                + sWt[1][w] * xb[sI[1][w] * CIN + c]
                + sWt[2][w] * xb[sI[2][w] * CIN + c]
                + sWt[3][w] * xb[sI[3][w] * CIN + c];
        g_A[rowbase + (long)w * KDIM] = s;
    }
}

// ---------------------------------------------------------------------------
// K3: fp32 SIMT GEMM  P[16384x256] = A[16384x2304] @ Wt[2304x256]
//     128x128 block tile, BK=8, 8x8 thread tile, register prefetch.
// ---------------------------------------------------------------------------
__global__ __launch_bounds__(256) void k_gemm() {
    __shared__ float As[8][128];
    __shared__ float Bs[8][128];

    int m0 = blockIdx.x * 128;
    int n0 = blockIdx.y * 128;
    int t  = threadIdx.x;
    int ty = t >> 4, tx = t & 15;

    const int arow = t >> 1, aseg = (t & 1) * 4;
    const int brow = t >> 5, bcol = (t & 31) * 4;

    float acc[8][8];
#pragma unroll
    for (int i = 0; i < 8; i++)
#pragma unroll
        for (int j = 0; j < 8; j++) acc[i][j] = 0.f;

    float4 av = *(const float4*)&g_A[(long)(m0 + arow) * KDIM + aseg];
    float4 bv = *(const float4*)&g_wt[brow * COUT + n0 + bcol];

    for (int kt = 0; kt < KDIM; kt += 8) {
        As[aseg + 0][arow] = av.x;
        As[aseg + 1][arow] = av.y;
        As[aseg + 2][arow] = av.z;
        As[aseg + 3][arow] = av.w;
        *(float4*)&Bs[brow][bcol] = bv;
        __syncthreads();

        int ktn = (kt + 8 < KDIM) ? kt + 8 : 0;
        av = *(const float4*)&g_A[(long)(m0 + arow) * KDIM + ktn + aseg];
        bv = *(const float4*)&g_wt[(ktn + brow) * COUT + n0 + bcol];

#pragma unroll
        for (int kk = 0; kk < 8; kk++) {
            float4 a0 = *(const float4*)&As[kk][ty * 4];
            float4 a1 = *(const float4*)&As[kk][64 + ty * 4];
            float4 b0 = *(const float4*)&Bs[kk][tx * 4];
            float4 b1 = *(const float4*)&Bs[kk][64 + tx * 4];
            float a[8] = {a0.x, a0.y, a0.z, a0.w, a1.x, a1.y, a1.z, a1.w};
            float bb[8] = {b0.x, b0.y, b0.z, b0.w, b1.x, b1.y, b1.z, b1.w};
#pragma unroll
            for (int i = 0; i < 8; i++)
#pragma unroll
                for (int j = 0; j < 8; j++)
                    acc[i][j] += a[i] * bb[j];
        }
        __syncthreads();
    }

#pragma unroll
    for (int i = 0; i < 8; i++) {
        int m = m0 + ((i < 4) ? (ty * 4 + i) : (64 + ty * 4 + i - 4));
        float4 c0 = make_float4(acc[i][0], acc[i][1], acc[i][2], acc[i][3]);
        float4 c1 = make_float4(acc[i][4], acc[i][5], acc[i][6], acc[i][7]);
        *(float4*)&g_P[(long)m * COUT + n0 + tx * 4] = c0;
        *(float4*)&g_P[(long)m * COUT + n0 + 64 + tx * 4] = c1;
    }
}

// ---------------------------------------------------------------------------
// K4: GroupNorm stats.  One block per (b, group); 8 channels x 4096 pixels.
// ---------------------------------------------------------------------------
__global__ __launch_bounds__(256) void k_gn_stats() {
    int b = blockIdx.x >> 5;
    int g = blockIdx.x & 31;
    int tid = threadIdx.x;
    float s = 0.f, ss = 0.f;
    for (int i = tid; i < HWSZ; i += 256) {
        const float* p = &g_P[(long)(b * HWSZ + i) * COUT + g * CPG];
        float4 u = *(const float4*)p;
        float4 v = *(const float4*)(p + 4);
        s  += u.x + u.y + u.z + u.w + v.x + v.y + v.z + v.w;
        ss += u.x * u.x + u.y * u.y + u.z * u.z + u.w * u.w
            + v.x * v.x + v.y * v.y + v.z * v.z + v.w * v.w;
    }
    __shared__ float rs[256], rss[256];
    rs[tid] = s; rss[tid] = ss;
    __syncthreads();
    for (int st = 128; st > 0; st >>= 1) {
        if (tid < st) { rs[tid] += rs[tid + st]; rss[tid] += rss[tid + st]; }
        __syncthreads();
    }
    if (tid == 0) {
        float inv = 1.f / (float)(CPG * HWSZ);
        float mean = rs[0] * inv;
        float var  = rss[0] * inv - mean * mean;
        g_stat[blockIdx.x * 2]     = mean;
        g_stat[blockIdx.x * 2 + 1] = rsqrtf(var + 1e-5f);
    }
}

// ---------------------------------------------------------------------------
// K5: normalize + affine + ReLU, with NHWC->NCHW transpose into d_out.
// ---------------------------------------------------------------------------
__global__ void k_gn_finalize(float* __restrict__ out,
                              const float* __restrict__ gamma,
                              const float* __restrict__ beta) {
    __shared__ float tile[32][33];
    int b   = blockIdx.z;
    int hw0 = blockIdx.x * 32;
    int o0  = blockIdx.y * 32;
    int tx = threadIdx.x, ty = threadIdx.y;

    int o = o0 + tx;
    int g = o >> 3;
    float mean = g_stat[(b * GROUPS + g) * 2];
    float rstd = g_stat[(b * GROUPS + g) * 2 + 1];
    float ga = gamma[o], be = beta[o];

#pragma unroll
    for (int i = 0; i < 4; i++) {
        int hw = hw0 + ty + i * 8;
        float v = g_P[(long)(b * HWSZ + hw) * COUT + o];
        v = (v - mean) * rstd * ga + be;
        tile[ty + i * 8][tx] = fmaxf(v, 0.f);
    }
    __syncthreads();
#pragma unroll
    for (int i = 0; i < 4; i++) {
        int oo = o0 + ty + i * 8;
        out[((long)b * COUT + oo) * HWSZ + hw0 + tx] = tile[tx][ty + i * 8];
    }
}

// ---------------------------------------------------------------------------
extern "C" void kernel_launch(void* const* d_in, const int* in_sizes, int n_in,
                              void* d_out, int out_size) {
    const float* x  = (const float*)d_in[0];
    const float* ow = (const float*)d_in[1];
    const float* ob = (const float*)d_in[2];
    const float* dw = (const float*)d_in[3];
    const float* ga = (const float*)d_in[4];
    const float* be = (const float*)d_in[5];
    float* out = (float*)d_out;

    k_transpose_x<<<dim3(HWSZ / 32, CIN / 32, BATCH), dim3(32, 8)>>>(x);
    k_transpose_w<<<(KDIM * COUT + 255) / 256, 256>>>(dw);
    k_offset_conv<<<dim3(WW / 16, HH / 16, BATCH), 256>>>(ow, ob);
    k_sample<<<BATCH * HH * KT, 256>>>();
    k_gemm<<<dim3(NPIX / 128, COUT / 128), 256>>>();
    k_gn_stats<<<BATCH * GROUPS, 256>>>();
    k_gn_finalize<<<dim3(HWSZ / 32, COUT / 32, BATCH), dim3(32, 8)>>>(out, ga, be);
}

// round 2
// speedup vs baseline: 2.1534x; 2.1534x over previous
#include <cuda_runtime.h>
#include <cstdint>

// ---------------------------------------------------------------------------
// DeformableBlock R2: tf32 tensor-core GEMM + vectorized sampler + split conv.
//   B=4, C=256, H=W=64.  offset conv3x3(256->18) -> bilinear im2col (tf32)
//   -> mma.sync tf32 GEMM [16384x2304]@[2304x256] -> GroupNorm(32)+ReLU.
// ---------------------------------------------------------------------------

#define BATCH 4
#define CIN   256
#define COUT  256
#define HH    64
#define WW    64
#define HWSZ  (HH*WW)          // 4096
#define NPIX  (BATCH*HWSZ)     // 16384
#define KT    9
#define KDIM  (KT*CIN)         // 2304
#define OCOFF 18
#define GROUPS 32
#define CPG   (COUT/GROUPS)    // 8

__device__ float g_xt  [NPIX * CIN];            // x NHWC
__device__ float g_off [NPIX * OCOFF];          // offsets
__device__ float g_offp[4][NPIX * OCOFF];       // offset partials (c-split)
__device__ float g_wt  [KDIM * COUT];           // W^T (tf32-rounded)
__device__ float g_A   [NPIX * KDIM];           // im2col (tf32-rounded)
__device__ float g_P   [NPIX * COUT];           // pre-GN result
__device__ float g_stat[BATCH * GROUPS * 2];    // mean / rstd

__device__ __forceinline__ float to_tf32(float x) {
    float r;
    asm("cvt.rna.tf32.f32 %0, %1;" : "=f"(r) : "f"(x));
    return r;
}
__device__ __forceinline__ unsigned sptr(const void* p) {
    return (unsigned)__cvta_generic_to_shared(p);
}
#define CP_ASYNC16(dst, src) \
    asm volatile("cp.async.cg.shared.global [%0], [%1], 16;\n" :: "r"(dst), "l"(src))
#define CP_COMMIT() asm volatile("cp.async.commit_group;\n")

// ---------------------------------------------------------------------------
// K0: x NCHW -> NHWC
// ---------------------------------------------------------------------------
__global__ void k_transpose_x(const float* __restrict__ x) {
    __shared__ float tile[32][33];
    int b = blockIdx.z, hw0 = blockIdx.x * 32, c0 = blockIdx.y * 32;
    int tx = threadIdx.x, ty = threadIdx.y;
#pragma unroll
    for (int i = 0; i < 4; i++) {
        int c = c0 + ty + i * 8;
        tile[ty + i * 8][tx] = x[((long)b * CIN + c) * HWSZ + hw0 + tx];
    }
    __syncthreads();
#pragma unroll
    for (int i = 0; i < 4; i++) {
        int hw = hw0 + ty + i * 8;
        g_xt[((long)b * HWSZ + hw) * CIN + c0 + tx] = tile[tx][ty + i * 8];
    }
}

// ---------------------------------------------------------------------------
// K0b: deform_w [O][C][3][3] -> g_wt[(k*256+c)*256 + o], tf32-rounded
// ---------------------------------------------------------------------------
__global__ void k_transpose_w(const float* __restrict__ dw) {
    int idx = blockIdx.x * blockDim.x + threadIdx.x;
    if (idx >= KDIM * COUT) return;
    int o = idx & 255;
    int c = (idx >> 8) & 255;
    int k = idx >> 16;
    g_wt[idx] = to_tf32(dw[(o * CIN + c) * KT + k]);
}

// ---------------------------------------------------------------------------
// K1: offset conv 3x3, C-split into 4 chunks of 64 (256 CTAs), partials out.
// ---------------------------------------------------------------------------
__global__ __launch_bounds__(256) void k_offset_conv(const float* __restrict__ ow) {
    int bz    = blockIdx.z;
    int b     = bz >> 2;
    int chunk = bz & 3;
    int x0 = blockIdx.x * 16, y0 = blockIdx.y * 16;
    int tid = threadIdx.x;
    int tx = tid & 15, ty = tid >> 4;

    __shared__ float sx[8][18][18];
    __shared__ float swf[8 * 9 * 20];

    float acc[20];
#pragma unroll
    for (int i = 0; i < 20; i++) acc[i] = 0.f;

    int cbeg = chunk * 64;
    for (int c0 = cbeg; c0 < cbeg + 64; c0 += 8) {
        for (int i = tid; i < 18 * 18 * 8; i += 256) {
            int cc = i & 7, p = i >> 3;
            int xx = p % 18, yy = p / 18;
            int gy = y0 + yy - 1, gx = x0 + xx - 1;
            float v = 0.f;
            if (gy >= 0 && gy < HH && gx >= 0 && gx < WW)
                v = g_xt[((b * HWSZ) + gy * WW + gx) * CIN + c0 + cc];
            sx[cc][yy][xx] = v;
        }
        for (int i = tid; i < 8 * 9 * 20; i += 256) {
            int oc = i % 20, j = (i / 20) % 9, cc = i / 180;
            swf[i] = (oc < OCOFF) ? ow[(oc * CIN + c0 + cc) * KT + j] : 0.f;
        }
        __syncthreads();
#pragma unroll
        for (int cc = 0; cc < 8; cc++) {
            float v[9];
#pragma unroll
            for (int j = 0; j < 9; j++)
                v[j] = sx[cc][ty + j / 3][tx + j % 3];
#pragma unroll
            for (int j = 0; j < 9; j++) {
                const float4* wp = reinterpret_cast<const float4*>(&swf[(cc * 9 + j) * 20]);
#pragma unroll
                for (int q = 0; q < 5; q++) {
                    float4 w = wp[q];
                    acc[q * 4 + 0] += v[j] * w.x;
                    acc[q * 4 + 1] += v[j] * w.y;
                    acc[q * 4 + 2] += v[j] * w.z;
                    acc[q * 4 + 3] += v[j] * w.w;
                }
            }
        }
        __syncthreads();
    }
    int pix = b * HWSZ + (y0 + ty) * WW + (x0 + tx);
#pragma unroll
    for (int oc = 0; oc < OCOFF; oc++)
        g_offp[chunk][pix * OCOFF + oc] = acc[oc];
}

__global__ void k_off_combine(const float* __restrict__ ob) {
    int i = blockIdx.x * 256 + threadIdx.x;
    if (i >= NPIX * OCOFF) return;
    int oc = i % OCOFF;
    g_off[i] = g_offp[0][i] + g_offp[1][i] + g_offp[2][i] + g_offp[3][i] + ob[oc];
}

// ---------------------------------------------------------------------------
// K2: bilinear im2col, float2-vectorized over channels, tf32-rounded output.
//     One block per (b, h, tap); 128 threads = 2 channels each.
// ---------------------------------------------------------------------------
__global__ __launch_bounds__(128) void k_sample() {
    int bk = blockIdx.x;
    int k  = bk % 9;
    int h  = (bk / 9) & 63;
    int b  = bk / (9 * 64);

    __shared__ int   sI[4][64];
    __shared__ float sWt[4][64];
    int tid = threadIdx.x;

    if (tid < 64) {
        int w = tid;
        int pix = b * HWSZ + h * WW + w;
        float dy = g_off[pix * OCOFF + 2 * k];
        float dx = g_off[pix * OCOFF + 2 * k + 1];
        int ky = k / 3, kx = k % 3;
        float py = (float)(h - 1 + ky) + dy;
        float px = (float)(w - 1 + kx) + dx;
        float y0f = floorf(py), x0f = floorf(px);
        float ty = py - y0f, tx = px - x0f;
        int y0 = (int)y0f, x0 = (int)x0f;
        int y1 = y0 + 1, x1 = x0 + 1;
        float vy0 = (y0 >= 0 && y0 < HH) ? 1.f : 0.f;
        float vy1 = (y1 >= 0 && y1 < HH) ? 1.f : 0.f;
        float vx0 = (x0 >= 0 && x0 < WW) ? 1.f : 0.f;
        float vx1 = (x1 >= 0 && x1 < WW) ? 1.f : 0.f;
        int yc0 = min(max(y0, 0), HH - 1), yc1 = min(max(y1, 0), HH - 1);
        int xc0 = min(max(x0, 0), WW - 1), xc1 = min(max(x1, 0), WW - 1);
        sI[0][w] = yc0 * WW + xc0;  sWt[0][w] = (1.f - ty) * (1.f - tx) * vy0 * vx0;
        sI[1][w] = yc0 * WW + xc1;  sWt[1][w] = (1.f - ty) * tx * vy0 * vx1;
        sI[2][w] = yc1 * WW + xc0;  sWt[2][w] = ty * (1.f - tx) * vy1 * vx0;
        sI[3][w] = yc1 * WW + xc1;  sWt[3][w] = ty * tx * vy1 * vx1;
    }
    __syncthreads();

    const float2* xb = reinterpret_cast<const float2*>(&g_xt[(long)b * HWSZ * CIN]);
    float2* Arow = reinterpret_cast<float2*>(
        &g_A[((long)(b * HWSZ + h * WW)) * KDIM + k * CIN]) + tid;
#pragma unroll 2
    for (int w = 0; w < 64; w++) {
        float2 v0 = xb[sI[0][w] * 128 + tid];
        float2 v1 = xb[sI[1][w] * 128 + tid];
        float2 v2 = xb[sI[2][w] * 128 + tid];
        float2 v3 = xb[sI[3][w] * 128 + tid];
        float w0 = sWt[0][w], w1 = sWt[1][w], w2 = sWt[2][w], w3 = sWt[3][w];
        float2 s;
        s.x = to_tf32(w0 * v0.x + w1 * v1.x + w2 * v2.x + w3 * v3.x);
        s.y = to_tf32(w0 * v0.y + w1 * v1.y + w2 * v2.y + w3 * v3.y);
        Arow[(long)w * (KDIM / 2)] = s;
    }
}

// ---------------------------------------------------------------------------
// K3: tf32 tensor-core GEMM  P[16384x256] = A[16384x2304] @ Wt[2304x256]
//     128x128 block tile, BK=16, cp.async double buffer,
//     8 warps -> 64x32 warp tiles of mma.sync.m16n8k8.tf32.
// ---------------------------------------------------------------------------
__global__ __launch_bounds__(256) void k_gemm_tf32() {
    __shared__ float As[2][128][20];   // [buf][m][k]  pad->20
    __shared__ float Bs[2][16][136];   // [buf][k][n]  pad->136 (stride%32==8)

    int m0 = blockIdx.x * 128;
    int n0 = blockIdx.y * 128;
    int t  = threadIdx.x;
    int wid = t >> 5, lane = t & 31;
    int wm = wid >> 2, wn = wid & 3;       // 2 x 4 warp grid
    int gp = lane >> 2, tg = lane & 3;

    float acc[4][4][4];
#pragma unroll
    for (int i = 0; i < 4; i++)
#pragma unroll
        for (int j = 0; j < 4; j++)
#pragma unroll
            for (int r = 0; r < 4; r++) acc[i][j][r] = 0.f;

    // per-thread cp.async assignments (2 A float4s + 2 B float4s per chunk)
    int af0 = t * 2, af1 = t * 2 + 1;
    int ar0 = af0 >> 2, ac0 = (af0 & 3) * 4;
    int ar1 = af1 >> 2, ac1 = (af1 & 3) * 4;
    int br0 = af0 >> 5, bc0 = (af0 & 31) * 4;
    int br1 = af1 >> 5, bc1 = (af1 & 31) * 4;

#define LOAD_CHUNK(buf, kt)                                                        \
    do {                                                                           \
        CP_ASYNC16(sptr(&As[buf][ar0][ac0]), &g_A[(long)(m0 + ar0) * KDIM + (kt) + ac0]); \
        CP_ASYNC16(sptr(&As[buf][ar1][ac1]), &g_A[(long)(m0 + ar1) * KDIM + (kt) + ac1]); \
        CP_ASYNC16(sptr(&Bs[buf][br0][bc0]), &g_wt[((kt) + br0) * COUT + n0 + bc0]);      \
        CP_ASYNC16(sptr(&Bs[buf][br1][bc1]), &g_wt[((kt) + br1) * COUT + n0 + bc1]);      \
        CP_COMMIT();                                                               \
    } while (0)

    LOAD_CHUNK(0, 0);

    const int NCHUNK = KDIM / 16;   // 144
    for (int c = 0; c < NCHUNK; c++) {
        int buf = c & 1;
        if (c + 1 < NCHUNK) {
            LOAD_CHUNK(buf ^ 1, (c + 1) * 16);
            asm volatile("cp.async.wait_group 1;\n");
        } else {
            asm volatile("cp.async.wait_group 0;\n");
        }
        __syncthreads();

        const float(*A)[20]  = As[buf];
        const float(*Bt)[136] = Bs[buf];
#pragma unroll
        for (int ks = 0; ks < 16; ks += 8) {
            uint32_t a[4][4], bb[4][2];
#pragma unroll
            for (int mt = 0; mt < 4; mt++) {
                int r = wm * 64 + mt * 16 + gp;
                a[mt][0] = __float_as_uint(A[r][ks + tg]);
                a[mt][1] = __float_as_uint(A[r + 8][ks + tg]);
                a[mt][2] = __float_as_uint(A[r][ks + tg + 4]);
                a[mt][3] = __float_as_uint(A[r + 8][ks + tg + 4]);
            }
#pragma unroll
            for (int nt = 0; nt < 4; nt++) {
                int ncol = wn * 32 + nt * 8 + gp;
                bb[nt][0] = __float_as_uint(Bt[ks + tg][ncol]);
                bb[nt][1] = __float_as_uint(Bt[ks + tg + 4][ncol]);
            }
#pragma unroll
            for (int mt = 0; mt < 4; mt++)
#pragma unroll
                for (int nt = 0; nt < 4; nt++) {
                    asm volatile(
                        "mma.sync.aligned.m16n8k8.row.col.f32.tf32.tf32.f32 "
                        "{%0,%1,%2,%3}, {%4,%5,%6,%7}, {%8,%9}, {%0,%1,%2,%3};\n"
                        : "+f"(acc[mt][nt][0]), "+f"(acc[mt][nt][1]),
                          "+f"(acc[mt][nt][2]), "+f"(acc[mt][nt][3])
                        : "r"(a[mt][0]), "r"(a[mt][1]), "r"(a[mt][2]), "r"(a[mt][3]),
                          "r"(bb[nt][0]), "r"(bb[nt][1]));
                }
        }
        __syncthreads();
    }

    // epilogue
#pragma unroll
    for (int mt = 0; mt < 4; mt++) {
        int r = m0 + wm * 64 + mt * 16 + gp;
#pragma unroll
        for (int nt = 0; nt < 4; nt++) {
            int col = n0 + wn * 32 + nt * 8 + tg * 2;
            *(float2*)&g_P[(long)r * COUT + col] =
                make_float2(acc[mt][nt][0], acc[mt][nt][1]);
            *(float2*)&g_P[(long)(r + 8) * COUT + col] =
                make_float2(acc[mt][nt][2], acc[mt][nt][3]);
        }
    }
#undef LOAD_CHUNK
}

// ---------------------------------------------------------------------------
// K4: GroupNorm stats
// ---------------------------------------------------------------------------
__global__ __launch_bounds__(256) void k_gn_stats() {
    int b = blockIdx.x >> 5;
    int g = blockIdx.x & 31;
    int tid = threadIdx.x;
    float s = 0.f, ss = 0.f;
    for (int i = tid; i < HWSZ; i += 256) {
        const float* p = &g_P[(long)(b * HWSZ + i) * COUT + g * CPG];
        float4 u = *(const float4*)p;
        float4 v = *(const float4*)(p + 4);
        s  += u.x + u.y + u.z + u.w + v.x + v.y + v.z + v.w;
        ss += u.x * u.x + u.y * u.y + u.z * u.z + u.w * u.w
            + v.x * v.x + v.y * v.y + v.z * v.z + v.w * v.w;
    }
    __shared__ float rs[256], rss[256];
    rs[tid] = s; rss[tid] = ss;
    __syncthreads();
    for (int st = 128; st > 0; st >>= 1) {
        if (tid < st) { rs[tid] += rs[tid + st]; rss[tid] += rss[tid + st]; }
        __syncthreads();
    }
    if (tid == 0) {
        float inv = 1.f / (float)(CPG * HWSZ);
        float mean = rs[0] * inv;
        float var  = rss[0] * inv - mean * mean;
        g_stat[blockIdx.x * 2]     = mean;
        g_stat[blockIdx.x * 2 + 1] = rsqrtf(var + 1e-5f);
    }
}

// ---------------------------------------------------------------------------
// K5: normalize + affine + ReLU + NHWC->NCHW into d_out
// ---------------------------------------------------------------------------
__global__ void k_gn_finalize(float* __restrict__ out,
                              const float* __restrict__ gamma,
                              const float* __restrict__ beta) {
    __shared__ float tile[32][33];
    int b = blockIdx.z, hw0 = blockIdx.x * 32, o0 = blockIdx.y * 32;
    int tx = threadIdx.x, ty = threadIdx.y;

    int o = o0 + tx;
    int g = o >> 3;
    float mean = g_stat[(b * GROUPS + g) * 2];
    float rstd = g_stat[(b * GROUPS + g) * 2 + 1];
    float ga = gamma[o], be = beta[o];

#pragma unroll
    for (int i = 0; i < 4; i++) {
        int hw = hw0 + ty + i * 8;
        float v = g_P[(long)(b * HWSZ + hw) * COUT + o];
        v = (v - mean) * rstd * ga + be;
        tile[ty + i * 8][tx] = fmaxf(v, 0.f);
    }
    __syncthreads();
#pragma unroll
    for (int i = 0; i < 4; i++) {
        int oo = o0 + ty + i * 8;
        out[((long)b * COUT + oo) * HWSZ + hw0 + tx] = tile[tx][ty + i * 8];
    }
}

// ---------------------------------------------------------------------------
extern "C" void kernel_launch(void* const* d_in, const int* in_sizes, int n_in,
                              void* d_out, int out_size) {
    const float* x  = (const float*)d_in[0];
    const float* ow = (const float*)d_in[1];
    const float* ob = (const float*)d_in[2];
    const float* dw = (const float*)d_in[3];
    const float* ga = (const float*)d_in[4];
    const float* be = (const float*)d_in[5];
    float* out = (float*)d_out;

    k_transpose_x<<<dim3(HWSZ / 32, CIN / 32, BATCH), dim3(32, 8)>>>(x);
    k_transpose_w<<<(KDIM * COUT + 255) / 256, 256>>>(dw);
    k_offset_conv<<<dim3(WW / 16, HH / 16, BATCH * 4), 256>>>(ow);
    k_off_combine<<<(NPIX * OCOFF + 255) / 256, 256>>>(ob);
    k_sample<<<BATCH * HH * KT, 128>>>();
    k_gemm_tf32<<<dim3(NPIX / 128, COUT / 128), 256>>>();
    k_gn_stats<<<BATCH * GROUPS, 256>>>();
    k_gn_finalize<<<dim3(HWSZ / 32, COUT / 32, BATCH), dim3(32, 8)>>>(out, ga, be);
}